// round 4
// baseline (speedup 1.0000x reference)
#include <cuda_runtime.h>
#include <cuda_fp16.h>
#include <cstdint>
#include <math.h>

// ---------------- Problem constants ----------------
#define T_TOK   1024
#define HDIM    1024
#define NEXP    64
#define TOPK    6
#define NGRP    8
#define TOPG    4
#define FDIM    512
#define FSH     1024
#define CAP     384
#define SCALE   2.5f

// ---------------- Device scratch ----------------
__device__ __align__(16) __half g_buf16 [(size_t)NEXP * CAP * HDIM];      // dispatch [E,CAP,H]
__device__ __align__(16) __half g_act16 [(size_t)NEXP * CAP * FDIM];      // act [E,CAP,F]
__device__ __align__(16) __half g_eo16  [(size_t)NEXP * CAP * HDIM];      // expert out fp16
__device__ __align__(16) __half g_x16   [(size_t)T_TOK * HDIM];
__device__ __align__(16) __half g_acts16[(size_t)T_TOK * FSH];
__device__ __align__(16) __half g_w13h  [(size_t)NEXP * HDIM * 2 * FDIM]; // [E][H][2F]
__device__ __align__(16) __half g_w2h   [(size_t)NEXP * FDIM * HDIM];     // [E][F][H]
__device__ __align__(16) __half g_sw13h [(size_t)HDIM * 2 * FSH];         // [H][2FSH]
__device__ __align__(16) __half g_sw2h  [(size_t)FSH * HDIM];             // [FSH][H]
__device__ int   g_cnt[NEXP];
__device__ int   g_ids[T_TOK * TOPK];
__device__ int   g_pos[T_TOK * TOPK];
__device__ float g_wts[T_TOK * TOPK];

// ---------------- PTX helpers ----------------
static __device__ __forceinline__ uint32_t s2u(const void* p) {
    uint32_t a;
    asm("{ .reg .u64 t; cvta.to.shared.u64 t, %1; cvt.u32.u64 %0, t; }" : "=r"(a) : "l"(p));
    return a;
}
#define CPA16(dst, src) asm volatile("cp.async.cg.shared.global [%0], [%1], 16;" :: "r"(dst), "l"(src))
#define CP_COMMIT()     asm volatile("cp.async.commit_group;")
#define CP_WAIT1()      asm volatile("cp.async.wait_group 1;")
#define CP_WAIT0()      asm volatile("cp.async.wait_group 0;")

#define LDSM4(r, addr) \
    asm volatile("ldmatrix.sync.aligned.m8n8.x4.shared.b16 {%0,%1,%2,%3}, [%4];" \
        : "=r"((r)[0]), "=r"((r)[1]), "=r"((r)[2]), "=r"((r)[3]) : "r"(addr))
#define LDSM4T(r, addr) \
    asm volatile("ldmatrix.sync.aligned.m8n8.x4.trans.shared.b16 {%0,%1,%2,%3}, [%4];" \
        : "=r"((r)[0]), "=r"((r)[1]), "=r"((r)[2]), "=r"((r)[3]) : "r"(addr))

#define MMA16816(d, a, b0, b1) \
    asm volatile("mma.sync.aligned.m16n8k16.row.col.f32.f16.f16.f32 " \
        "{%0,%1,%2,%3}, {%4,%5,%6,%7}, {%8,%9}, {%0,%1,%2,%3};" \
        : "+f"((d)[0]), "+f"((d)[1]), "+f"((d)[2]), "+f"((d)[3]) \
        : "r"((a)[0]), "r"((a)[1]), "r"((a)[2]), "r"((a)[3]), "r"(b0), "r"(b1))

// SMEM tile geometry (halves)
#define LDA_S 40     // 32 k + 8 pad
#define LDB_S 136    // 128 n + 8 pad
#define ABUF  (128 * LDA_S)
#define BBUF  (32 * LDB_S)

// ---------------- Gate + grouped top-k (exact fp32) ----------------
__global__ void gate_topk_kernel(const float* __restrict__ x,
                                 const float* __restrict__ gw,
                                 const float* __restrict__ bias)
{
    __shared__ float xs[HDIM];
    __shared__ float scores[NEXP];
    __shared__ float sc[NEXP];
    int t = blockIdx.x;
    for (int i = threadIdx.x; i < HDIM; i += blockDim.x) xs[i] = x[(size_t)t * HDIM + i];
    __syncthreads();
    int e = threadIdx.x;
    const float* g = gw + (size_t)e * HDIM;
    float acc = 0.f;
    #pragma unroll 8
    for (int i = 0; i < HDIM; i++) acc = fmaf(xs[i], g[i], acc);
    float s = 1.f / (1.f + expf(-acc));
    scores[e] = s;
    sc[e] = s + bias[e];
    __syncthreads();
    if (threadIdx.x == 0) {
        float gs[NGRP];
        for (int gi = 0; gi < NGRP; gi++) {
            float m1 = -1e30f, m2 = -1e30f;
            for (int j = 0; j < 8; j++) {
                float v = sc[gi * 8 + j];
                if (v > m1) { m2 = m1; m1 = v; } else if (v > m2) m2 = v;
            }
            gs[gi] = m1 + m2;
        }
        bool gsel[NGRP];
        for (int gi = 0; gi < NGRP; gi++) gsel[gi] = false;
        for (int r = 0; r < TOPG; r++) {
            int bi = -1; float bv = -1e30f;
            for (int gi = 0; gi < NGRP; gi++)
                if (!gsel[gi] && gs[gi] > bv) { bv = gs[gi]; bi = gi; }
            gsel[bi] = true;
        }
        float masked[NEXP];
        for (int i = 0; i < NEXP; i++) masked[i] = gsel[i >> 3] ? sc[i] : -1e30f;
        int id[TOPK]; float wsum = 0.f;
        for (int r = 0; r < TOPK; r++) {
            int bi = -1; float bv = -1e30f;
            for (int i = 0; i < NEXP; i++)
                if (masked[i] > bv) { bv = masked[i]; bi = i; }
            masked[bi] = -1e30f;
            id[r] = bi;
            wsum += scores[bi];
        }
        float inv = SCALE / wsum;
        for (int r = 0; r < TOPK; r++) {
            g_ids[t * TOPK + r] = id[r];
            g_wts[t * TOPK + r] = scores[id[r]] * inv;
        }
    }
}

__global__ void zero_cnt_kernel() { if (threadIdx.x < NEXP) g_cnt[threadIdx.x] = 0; }

__global__ void assign_kernel() {
    int i = blockIdx.x * blockDim.x + threadIdx.x;
    if (i < T_TOK * TOPK) g_pos[i] = atomicAdd(&g_cnt[g_ids[i]], 1);
}

__global__ void scatter16_kernel(const float* __restrict__ x) {
    int i = blockIdx.x;
    int p = g_pos[i];
    if (p >= CAP) return;
    int e = g_ids[i];
    int t = i / TOPK;
    const float4* src = (const float4*)(x + (size_t)t * HDIM);
    __half* dst = g_buf16 + ((size_t)e * CAP + p) * HDIM;
    for (int j = threadIdx.x; j < HDIM / 4; j += blockDim.x) {
        float4 v = src[j];
        __half2 a = __floats2half2_rn(v.x, v.y);
        __half2 b = __floats2half2_rn(v.z, v.w);
        uint2 u = make_uint2(*(uint32_t*)&a, *(uint32_t*)&b);
        *(uint2*)(dst + j * 4) = u;
    }
}

__global__ void conv16_kernel(const float* __restrict__ in, __half* __restrict__ out, int n4) {
    int i = blockIdx.x * blockDim.x + threadIdx.x;
    if (i < n4) {
        float4 v = ((const float4*)in)[i];
        __half2 a = __floats2half2_rn(v.x, v.y);
        __half2 b = __floats2half2_rn(v.z, v.w);
        uint2 u = make_uint2(*(uint32_t*)&a, *(uint32_t*)&b);
        *(uint2*)(out + (size_t)i * 4) = u;
    }
}

// ---------------- Fused up-proj + SiLU*Mul (mma.sync fp16) ----------------
__global__ __launch_bounds__(256, 2)
void gemm13_mma(const __half* __restrict__ A0, int lda, size_t sAe,
                const __half* __restrict__ B0, int ldb, size_t sBe, int halfOff,
                __half* __restrict__ C0, int ldc, size_t sCe,
                int Kdim, const int* __restrict__ cnt)
{
    __shared__ __align__(16) __half As[2 * ABUF];
    __shared__ __align__(16) __half Bs[2 * BBUF];

    int e = blockIdx.y;
    int m0 = blockIdx.z * 128;
    if (cnt && m0 >= cnt[e]) return;
    int n0 = blockIdx.x * 64;

    int tid = threadIdx.x;
    int warp = tid >> 5, lane = tid & 31;
    int mw = warp & 1, nw = warp >> 1;

    const __half* A = A0 + (size_t)e * sAe + (size_t)m0 * lda;
    const __half* B = B0 + (size_t)e * sBe;
    uint32_t AsU = s2u(As), BsU = s2u(Bs);

    float accg[4][2][4] = {}, accu[4][2][4] = {};

    auto load_tiles = [&](int b, int k0) {
        int ar = tid >> 1, ac = (tid & 1) * 2;
        const __half* Ag = A + (size_t)ar * lda + k0;
        uint32_t Ad = AsU + (uint32_t)(b * ABUF + ar * LDA_S) * 2;
        CPA16(Ad + ac * 16u, Ag + ac * 8);
        CPA16(Ad + (ac + 1) * 16u, Ag + (ac + 1) * 8);
        int br = tid >> 3, cc = tid & 7;
        const __half* Bg = B + (size_t)(k0 + br) * ldb;
        uint32_t Bd = BsU + (uint32_t)(b * BBUF + br * LDB_S) * 2;
        CPA16(Bd + cc * 16u, Bg + n0 + cc * 8);
        CPA16(Bd + (64 + cc * 8) * 2u, Bg + halfOff + n0 + cc * 8);
    };

    int NC = Kdim / 32;
    load_tiles(0, 0);
    CP_COMMIT();
    for (int i = 0; i < NC; i++) {
        int b = i & 1;
        if (i + 1 < NC) { load_tiles(b ^ 1, (i + 1) * 32); CP_COMMIT(); CP_WAIT1(); }
        else CP_WAIT0();
        __syncthreads();

        uint32_t ab = AsU + (uint32_t)(b * ABUF) * 2;
        uint32_t bb = BsU + (uint32_t)(b * BBUF) * 2;
        #pragma unroll
        for (int ks = 0; ks < 32; ks += 16) {
            uint32_t af[4][4];
            #pragma unroll
            for (int mi = 0; mi < 4; mi++) {
                int r = mw * 64 + mi * 16 + (lane & 15);
                LDSM4(af[mi], ab + (uint32_t)(r * LDA_S + ks + (lane >> 4) * 8) * 2);
            }
            uint32_t bg[4], bu[4];
            int kr = ks + (lane & 15);
            LDSM4T(bg, bb + (uint32_t)(kr * LDB_S + nw * 16 + (lane >> 4) * 8) * 2);
            LDSM4T(bu, bb + (uint32_t)(kr * LDB_S + 64 + nw * 16 + (lane >> 4) * 8) * 2);
            #pragma unroll
            for (int mi = 0; mi < 4; mi++) {
                MMA16816(accg[mi][0], af[mi], bg[0], bg[1]);
                MMA16816(accg[mi][1], af[mi], bg[2], bg[3]);
                MMA16816(accu[mi][0], af[mi], bu[0], bu[1]);
                MMA16816(accu[mi][1], af[mi], bu[2], bu[3]);
            }
        }
        __syncthreads();
    }

    int g = lane >> 2, c = lane & 3;
    #pragma unroll
    for (int mi = 0; mi < 4; mi++) {
        #pragma unroll
        for (int j = 0; j < 2; j++) {
            float* G = accg[mi][j];
            float* U = accu[mi][j];
            int col = n0 + nw * 16 + j * 8 + 2 * c;
            int r0 = m0 + mw * 64 + mi * 16 + g;
            float s0 = G[0] / (1.f + expf(-G[0])) * U[0];
            float s1 = G[1] / (1.f + expf(-G[1])) * U[1];
            float s2 = G[2] / (1.f + expf(-G[2])) * U[2];
            float s3 = G[3] / (1.f + expf(-G[3])) * U[3];
            __half2 h0 = __floats2half2_rn(s0, s1);
            __half2 h1 = __floats2half2_rn(s2, s3);
            *(__half2*)(C0 + (size_t)e * sCe + (size_t)r0 * ldc + col) = h0;
            *(__half2*)(C0 + (size_t)e * sCe + (size_t)(r0 + 8) * ldc + col) = h1;
        }
    }
}

// ---------------- Plain GEMM (mma.sync fp16) — templated output type ----------------
template <typename OutT>
__global__ __launch_bounds__(256, 2)
void gemm2_mma(const __half* __restrict__ A0, int lda, size_t sAe,
               const __half* __restrict__ B0, int ldb, size_t sBe,
               OutT* __restrict__ C0, int ldc, size_t sCe,
               int Kdim, const int* __restrict__ cnt)
{
    __shared__ __align__(16) __half As[2 * ABUF];
    __shared__ __align__(16) __half Bs[2 * BBUF];

    int e = blockIdx.y;
    int m0 = blockIdx.z * 128;
    if (cnt && m0 >= cnt[e]) return;
    int n0 = blockIdx.x * 128;

    int tid = threadIdx.x;
    int warp = tid >> 5, lane = tid & 31;
    int mw = warp & 1, nw = warp >> 1;

    const __half* A = A0 + (size_t)e * sAe + (size_t)m0 * lda;
    const __half* B = B0 + (size_t)e * sBe;
    uint32_t AsU = s2u(As), BsU = s2u(Bs);

    float acc[4][4][4] = {};

    auto load_tiles = [&](int b, int k0) {
        int ar = tid >> 1, ac = (tid & 1) * 2;
        const __half* Ag = A + (size_t)ar * lda + k0;
        uint32_t Ad = AsU + (uint32_t)(b * ABUF + ar * LDA_S) * 2;
        CPA16(Ad + ac * 16u, Ag + ac * 8);
        CPA16(Ad + (ac + 1) * 16u, Ag + (ac + 1) * 8);
        int br = tid >> 3, cc = tid & 7;
        const __half* Bg = B + (size_t)(k0 + br) * ldb + n0;
        uint32_t Bd = BsU + (uint32_t)(b * BBUF + br * LDB_S) * 2;
        CPA16(Bd + cc * 16u, Bg + cc * 8);
        CPA16(Bd + (cc + 8) * 16u, Bg + (cc + 8) * 8);
    };

    int NC = Kdim / 32;
    load_tiles(0, 0);
    CP_COMMIT();
    for (int i = 0; i < NC; i++) {
        int b = i & 1;
        if (i + 1 < NC) { load_tiles(b ^ 1, (i + 1) * 32); CP_COMMIT(); CP_WAIT1(); }
        else CP_WAIT0();
        __syncthreads();

        uint32_t ab = AsU + (uint32_t)(b * ABUF) * 2;
        uint32_t bb = BsU + (uint32_t)(b * BBUF) * 2;
        #pragma unroll
        for (int ks = 0; ks < 32; ks += 16) {
            uint32_t af[4][4];
            #pragma unroll
            for (int mi = 0; mi < 4; mi++) {
                int r = mw * 64 + mi * 16 + (lane & 15);
                LDSM4(af[mi], ab + (uint32_t)(r * LDA_S + ks + (lane >> 4) * 8) * 2);
            }
            uint32_t bf0[4], bf1[4];
            int kr = ks + (lane & 15);
            LDSM4T(bf0, bb + (uint32_t)(kr * LDB_S + nw * 32 + (lane >> 4) * 8) * 2);
            LDSM4T(bf1, bb + (uint32_t)(kr * LDB_S + nw * 32 + 16 + (lane >> 4) * 8) * 2);
            #pragma unroll
            for (int mi = 0; mi < 4; mi++) {
                MMA16816(acc[mi][0], af[mi], bf0[0], bf0[1]);
                MMA16816(acc[mi][1], af[mi], bf0[2], bf0[3]);
                MMA16816(acc[mi][2], af[mi], bf1[0], bf1[1]);
                MMA16816(acc[mi][3], af[mi], bf1[2], bf1[3]);
            }
        }
        __syncthreads();
    }

    int g = lane >> 2, c = lane & 3;
    #pragma unroll
    for (int mi = 0; mi < 4; mi++) {
        #pragma unroll
        for (int j = 0; j < 4; j++) {
            float* D = acc[mi][j];
            int col = n0 + nw * 32 + j * 8 + 2 * c;
            int r0 = m0 + mw * 64 + mi * 16 + g;
            OutT* Cb = C0 + (size_t)e * sCe;
            if constexpr (sizeof(OutT) == 4) {
                *(float2*)((float*)Cb + (size_t)r0 * ldc + col) = make_float2(D[0], D[1]);
                *(float2*)((float*)Cb + (size_t)(r0 + 8) * ldc + col) = make_float2(D[2], D[3]);
            } else {
                *(__half2*)((__half*)Cb + (size_t)r0 * ldc + col) = __floats2half2_rn(D[0], D[1]);
                *(__half2*)((__half*)Cb + (size_t)(r0 + 8) * ldc + col) = __floats2half2_rn(D[2], D[3]);
            }
        }
    }
}

// ---------------- Combine (eo fp16) ----------------
__global__ void combine_kernel(float* __restrict__ out) {
    int t = blockIdx.x;
    int h = threadIdx.x;          // 256 threads x 4 elems
    int ids[TOPK], pos[TOPK]; float w[TOPK];
    #pragma unroll
    for (int k = 0; k < TOPK; k++) {
        ids[k] = g_ids[t * TOPK + k];
        pos[k] = g_pos[t * TOPK + k];
        w[k]   = g_wts[t * TOPK + k];
    }
    float4* o4 = (float4*)(out + (size_t)t * HDIM);
    float4 acc = o4[h];
    #pragma unroll
    for (int k = 0; k < TOPK; k++) {
        if (pos[k] < CAP) {
            const uint2* v2 = (const uint2*)(g_eo16 + ((size_t)ids[k] * CAP + pos[k]) * HDIM);
            uint2 u = v2[h];
            __half2 a = *(__half2*)&u.x;
            __half2 b = *(__half2*)&u.y;
            float2 fa = __half22float2(a);
            float2 fb = __half22float2(b);
            acc.x = fmaf(w[k], fa.x, acc.x);
            acc.y = fmaf(w[k], fa.y, acc.y);
            acc.z = fmaf(w[k], fb.x, acc.z);
            acc.w = fmaf(w[k], fb.y, acc.w);
        }
    }
    o4[h] = acc;
}

// ---------------- Launch ----------------
extern "C" void kernel_launch(void* const* d_in, const int* in_sizes, int n_in,
                              void* d_out, int out_size)
{
    const float* x      = (const float*)d_in[0];
    const float* gate_w = (const float*)d_in[1];
    const float* bias   = (const float*)d_in[2];
    const float* w13    = (const float*)d_in[3];
    const float* w2     = (const float*)d_in[4];
    const float* sw13   = (const float*)d_in[5];
    const float* sw2    = (const float*)d_in[6];
    float* out = (float*)d_out;

    __half *buf16, *act16, *eo16, *x16, *acts16, *w13h, *w2h, *sw13h, *sw2h;
    int* cnt;
    cudaGetSymbolAddress((void**)&buf16,  g_buf16);
    cudaGetSymbolAddress((void**)&act16,  g_act16);
    cudaGetSymbolAddress((void**)&eo16,   g_eo16);
    cudaGetSymbolAddress((void**)&x16,    g_x16);
    cudaGetSymbolAddress((void**)&acts16, g_acts16);
    cudaGetSymbolAddress((void**)&w13h,   g_w13h);
    cudaGetSymbolAddress((void**)&w2h,    g_w2h);
    cudaGetSymbolAddress((void**)&sw13h,  g_sw13h);
    cudaGetSymbolAddress((void**)&sw2h,   g_sw2h);
    cudaGetSymbolAddress((void**)&cnt,    g_cnt);

    // lazy-init side streams + fork/join events (resources only; work is identical every call)
    static cudaStream_t s1 = nullptr, s2 = nullptr;
    static cudaEvent_t evA = nullptr, evW13 = nullptr, evW2 = nullptr, evSh = nullptr;
    if (!s1) {
        cudaStreamCreateWithFlags(&s1, cudaStreamNonBlocking);
        cudaStreamCreateWithFlags(&s2, cudaStreamNonBlocking);
        cudaEventCreateWithFlags(&evA,   cudaEventDisableTiming);
        cudaEventCreateWithFlags(&evW13, cudaEventDisableTiming);
        cudaEventCreateWithFlags(&evW2,  cudaEventDisableTiming);
        cudaEventCreateWithFlags(&evSh,  cudaEventDisableTiming);
    }

    // fork
    cudaEventRecord(evA, 0);
    cudaStreamWaitEvent(s1, evA, 0);
    cudaStreamWaitEvent(s2, evA, 0);

    // ---- stream s1: big weight converts ----
    {
        int n4 = NEXP * HDIM * 2 * FDIM / 4;
        conv16_kernel<<<(n4 + 255) / 256, 256, 0, s1>>>(w13, w13h, n4);
        cudaEventRecord(evW13, s1);
        n4 = NEXP * FDIM * HDIM / 4;
        conv16_kernel<<<(n4 + 255) / 256, 256, 0, s1>>>(w2, w2h, n4);
        cudaEventRecord(evW2, s1);
    }

    // ---- stream s2: shared-expert chain ----
    {
        conv16_kernel<<<(T_TOK * HDIM / 4 + 255) / 256, 256, 0, s2>>>(x, x16, T_TOK * HDIM / 4);
        int n4 = HDIM * 2 * FSH / 4;
        conv16_kernel<<<(n4 + 255) / 256, 256, 0, s2>>>(sw13, sw13h, n4);
        gemm13_mma<<<dim3(FSH / 64, 1, T_TOK / 128), 256, 0, s2>>>(
            x16, HDIM, 0, sw13h, 2 * FSH, 0, FSH, acts16, FSH, 0, HDIM, nullptr);
        n4 = FSH * HDIM / 4;
        conv16_kernel<<<(n4 + 255) / 256, 256, 0, s2>>>(sw2, sw2h, n4);
        gemm2_mma<float><<<dim3(HDIM / 128, 1, T_TOK / 128), 256, 0, s2>>>(
            acts16, FSH, 0, sw2h, HDIM, 0, out, HDIM, 0, FSH, nullptr);
        cudaEventRecord(evSh, s2);
    }

    // ---- main stream: routing + routed experts ----
    gate_topk_kernel<<<T_TOK, 64>>>(x, gate_w, bias);
    zero_cnt_kernel<<<1, 64>>>();
    assign_kernel<<<(T_TOK * TOPK + 255) / 256, 256>>>();
    scatter16_kernel<<<T_TOK * TOPK, 128>>>(x);

    cudaStreamWaitEvent(0, evW13, 0);
    gemm13_mma<<<dim3(FDIM / 64, NEXP, CAP / 128), 256>>>(
        buf16, HDIM, (size_t)CAP * HDIM,
        w13h, 2 * FDIM, (size_t)HDIM * 2 * FDIM, FDIM,
        act16, FDIM, (size_t)CAP * FDIM,
        HDIM, cnt);

    cudaStreamWaitEvent(0, evW2, 0);
    gemm2_mma<__half><<<dim3(HDIM / 128, NEXP, CAP / 128), 256>>>(
        act16, FDIM, (size_t)CAP * FDIM,
        w2h, HDIM, (size_t)FDIM * HDIM,
        eo16, HDIM, (size_t)CAP * HDIM,
        FDIM, cnt);

    // join shared branch, then combine
    cudaStreamWaitEvent(0, evSh, 0);
    combine_kernel<<<T_TOK, 256>>>(out);
}

// round 5
// speedup vs baseline: 1.1470x; 1.1470x over previous
#include <cuda_runtime.h>
#include <cuda_fp16.h>
#include <cstdint>
#include <math.h>

// ---------------- Problem constants ----------------
#define T_TOK   1024
#define HDIM    1024
#define NEXP    64
#define TOPK    6
#define NGRP    8
#define TOPG    4
#define FDIM    512
#define FSH     1024
#define CAP     384
#define SCALE   2.5f

// ---------------- Device scratch ----------------
__device__ __align__(16) __half g_buf16 [(size_t)NEXP * CAP * HDIM];      // dispatch [E,CAP,H]
__device__ __align__(16) __half g_act16 [(size_t)NEXP * CAP * FDIM];      // act [E,CAP,F]
__device__ __align__(16) __half g_eo16  [(size_t)NEXP * CAP * HDIM];      // expert out fp16
__device__ __align__(16) __half g_x16   [(size_t)T_TOK * HDIM];
__device__ __align__(16) __half g_acts16[(size_t)T_TOK * FSH];
__device__ int   g_cnt[NEXP];
__device__ int   g_ids[T_TOK * TOPK];
__device__ int   g_pos[T_TOK * TOPK];
__device__ float g_wts[T_TOK * TOPK];

// ---------------- PTX helpers ----------------
static __device__ __forceinline__ uint32_t s2u(const void* p) {
    uint32_t a;
    asm("{ .reg .u64 t; cvta.to.shared.u64 t, %1; cvt.u32.u64 %0, t; }" : "=r"(a) : "l"(p));
    return a;
}
#define LDSM4(r, addr) \
    asm volatile("ldmatrix.sync.aligned.m8n8.x4.shared.b16 {%0,%1,%2,%3}, [%4];" \
        : "=r"((r)[0]), "=r"((r)[1]), "=r"((r)[2]), "=r"((r)[3]) : "r"(addr))
#define LDSM4T(r, addr) \
    asm volatile("ldmatrix.sync.aligned.m8n8.x4.trans.shared.b16 {%0,%1,%2,%3}, [%4];" \
        : "=r"((r)[0]), "=r"((r)[1]), "=r"((r)[2]), "=r"((r)[3]) : "r"(addr))
#define MMA16816(d, a, b0, b1) \
    asm volatile("mma.sync.aligned.m16n8k16.row.col.f32.f16.f16.f32 " \
        "{%0,%1,%2,%3}, {%4,%5,%6,%7}, {%8,%9}, {%0,%1,%2,%3};" \
        : "+f"((d)[0]), "+f"((d)[1]), "+f"((d)[2]), "+f"((d)[3]) \
        : "r"((a)[0]), "r"((a)[1]), "r"((a)[2]), "r"((a)[3]), "r"(b0), "r"(b1))

// SMEM tile geometry (halves)
#define LDA_S 40     // 32 k + 8 pad
#define LDB_S 136    // 128 n + 8 pad
#define ABUF  (128 * LDA_S)
#define BBUF  (32 * LDB_S)

// ---------------- Gate + grouped top-k (exact fp32) ----------------
__global__ void gate_topk_kernel(const float* __restrict__ x,
                                 const float* __restrict__ gw,
                                 const float* __restrict__ bias)
{
    __shared__ float xs[HDIM];
    __shared__ float scores[NEXP];
    __shared__ float sc[NEXP];
    int t = blockIdx.x;
    for (int i = threadIdx.x; i < HDIM; i += blockDim.x) xs[i] = x[(size_t)t * HDIM + i];
    __syncthreads();
    int e = threadIdx.x;
    const float* g = gw + (size_t)e * HDIM;
    float acc = 0.f;
    #pragma unroll 8
    for (int i = 0; i < HDIM; i++) acc = fmaf(xs[i], g[i], acc);
    float s = 1.f / (1.f + expf(-acc));
    scores[e] = s;
    sc[e] = s + bias[e];
    __syncthreads();
    if (threadIdx.x == 0) {
        float gs[NGRP];
        for (int gi = 0; gi < NGRP; gi++) {
            float m1 = -1e30f, m2 = -1e30f;
            for (int j = 0; j < 8; j++) {
                float v = sc[gi * 8 + j];
                if (v > m1) { m2 = m1; m1 = v; } else if (v > m2) m2 = v;
            }
            gs[gi] = m1 + m2;
        }
        bool gsel[NGRP];
        for (int gi = 0; gi < NGRP; gi++) gsel[gi] = false;
        for (int r = 0; r < TOPG; r++) {
            int bi = -1; float bv = -1e30f;
            for (int gi = 0; gi < NGRP; gi++)
                if (!gsel[gi] && gs[gi] > bv) { bv = gs[gi]; bi = gi; }
            gsel[bi] = true;
        }
        float masked[NEXP];
        for (int i = 0; i < NEXP; i++) masked[i] = gsel[i >> 3] ? sc[i] : -1e30f;
        int id[TOPK]; float wsum = 0.f;
        for (int r = 0; r < TOPK; r++) {
            int bi = -1; float bv = -1e30f;
            for (int i = 0; i < NEXP; i++)
                if (masked[i] > bv) { bv = masked[i]; bi = i; }
            masked[bi] = -1e30f;
            id[r] = bi;
            wsum += scores[bi];
        }
        float inv = SCALE / wsum;
        for (int r = 0; r < TOPK; r++) {
            g_ids[t * TOPK + r] = id[r];
            g_wts[t * TOPK + r] = scores[id[r]] * inv;
        }
    }
}

__global__ void zero_cnt_kernel() { if (threadIdx.x < NEXP) g_cnt[threadIdx.x] = 0; }

__global__ void assign_kernel() {
    int i = blockIdx.x * blockDim.x + threadIdx.x;
    if (i < T_TOK * TOPK) g_pos[i] = atomicAdd(&g_cnt[g_ids[i]], 1);
}

__global__ void scatter16_kernel(const float* __restrict__ x) {
    int i = blockIdx.x;
    int p = g_pos[i];
    if (p >= CAP) return;
    int e = g_ids[i];
    int t = i / TOPK;
    const float4* src = (const float4*)(x + (size_t)t * HDIM);
    __half* dst = g_buf16 + ((size_t)e * CAP + p) * HDIM;
    for (int j = threadIdx.x; j < HDIM / 4; j += blockDim.x) {
        float4 v = src[j];
        __half2 a = __floats2half2_rn(v.x, v.y);
        __half2 b = __floats2half2_rn(v.z, v.w);
        uint2 u = make_uint2(*(uint32_t*)&a, *(uint32_t*)&b);
        *(uint2*)(dst + j * 4) = u;
    }
}

__global__ void conv16_kernel(const float* __restrict__ in, __half* __restrict__ out, int n4) {
    int i = blockIdx.x * blockDim.x + threadIdx.x;
    if (i < n4) {
        float4 v = ((const float4*)in)[i];
        __half2 a = __floats2half2_rn(v.x, v.y);
        __half2 b = __floats2half2_rn(v.z, v.w);
        uint2 u = make_uint2(*(uint32_t*)&a, *(uint32_t*)&b);
        *(uint2*)(out + (size_t)i * 4) = u;
    }
}

// convert 4 fp32 (float4) -> uint2 of 4 halves
static __device__ __forceinline__ uint2 f4h(float4 v) {
    __half2 a = __floats2half2_rn(v.x, v.y);
    __half2 b = __floats2half2_rn(v.z, v.w);
    return make_uint2(*(uint32_t*)&a, *(uint32_t*)&b);
}

// ---------------- Fused up-proj + SiLU*Mul: A fp16, B fp32 (in-kernel cvt) ----------------
// B [K][2F] fp32 row-major; SMEM B tile 32k x (64 gate | 64 up) halves.
__global__ __launch_bounds__(256, 2)
void gemm13_mma(const __half* __restrict__ A0, int lda, size_t sAe,
                const float* __restrict__ B0, int ldb, size_t sBe, int halfOff,
                __half* __restrict__ C0, int ldc, size_t sCe,
                int Kdim, const int* __restrict__ cnt)
{
    __shared__ __align__(16) __half As[2 * ABUF];
    __shared__ __align__(16) __half Bs[2 * BBUF];

    int e = blockIdx.z;
    int m0 = blockIdx.y * 128;
    if (cnt && m0 >= cnt[e]) return;
    int n0 = blockIdx.x * 64;

    int tid = threadIdx.x;
    int warp = tid >> 5, lane = tid & 31;
    int mw = warp & 1, nw = warp >> 1;

    const __half* A = A0 + (size_t)e * sAe + (size_t)m0 * lda;
    const float*  B = B0 + (size_t)e * sBe;
    uint32_t AsU = s2u(As), BsU = s2u(Bs);

    // staging thread maps
    int ar = tid >> 1, acol = (tid & 1) * 16;          // A: 128 rows x 32 halves
    int br = tid >> 3, sg = tid & 7;                   // B: 32 rows x 8 segs of 16 floats
    int bcolg = (sg < 4) ? (n0 + sg * 16) : (halfOff + n0 + (sg - 4) * 16);
    int bcols = (sg < 4) ? (sg * 16) : (64 + (sg - 4) * 16);
    const __half* Ag = A + (size_t)ar * lda + acol;
    const float*  Bg = B + (size_t)br * ldb + bcolg;

    float accg[4][2][4] = {}, accu[4][2][4] = {};
    uint4 ra[2]; uint2 rbh[4];

    auto ldg = [&](int k0) {
        const uint4* ap = (const uint4*)(Ag + k0);
        ra[0] = ap[0]; ra[1] = ap[1];
        const float4* bp = (const float4*)(Bg + (size_t)k0 * ldb);
        rbh[0] = f4h(bp[0]); rbh[1] = f4h(bp[1]); rbh[2] = f4h(bp[2]); rbh[3] = f4h(bp[3]);
    };
    auto sts = [&](int b) {
        uint4* ad = (uint4*)(As + b * ABUF + ar * LDA_S + acol);
        ad[0] = ra[0]; ad[1] = ra[1];
        uint4* bd = (uint4*)(Bs + b * BBUF + br * LDB_S + bcols);
        bd[0] = make_uint4(rbh[0].x, rbh[0].y, rbh[1].x, rbh[1].y);
        bd[1] = make_uint4(rbh[2].x, rbh[2].y, rbh[3].x, rbh[3].y);
    };

    int NC = Kdim / 32;
    ldg(0);
    for (int i = 0; i < NC; i++) {
        int b = i & 1;
        sts(b);
        __syncthreads();
        if (i + 1 < NC) ldg((i + 1) * 32);

        uint32_t ab = AsU + (uint32_t)(b * ABUF) * 2;
        uint32_t bb = BsU + (uint32_t)(b * BBUF) * 2;
        #pragma unroll
        for (int ks = 0; ks < 32; ks += 16) {
            uint32_t af[4][4];
            #pragma unroll
            for (int mi = 0; mi < 4; mi++) {
                int r = mw * 64 + mi * 16 + (lane & 15);
                LDSM4(af[mi], ab + (uint32_t)(r * LDA_S + ks + (lane >> 4) * 8) * 2);
            }
            uint32_t bgf[4], buf[4];
            int kr = ks + (lane & 15);
            LDSM4T(bgf, bb + (uint32_t)(kr * LDB_S + nw * 16 + (lane >> 4) * 8) * 2);
            LDSM4T(buf, bb + (uint32_t)(kr * LDB_S + 64 + nw * 16 + (lane >> 4) * 8) * 2);
            #pragma unroll
            for (int mi = 0; mi < 4; mi++) {
                MMA16816(accg[mi][0], af[mi], bgf[0], bgf[1]);
                MMA16816(accg[mi][1], af[mi], bgf[2], bgf[3]);
                MMA16816(accu[mi][0], af[mi], buf[0], buf[1]);
                MMA16816(accu[mi][1], af[mi], buf[2], buf[3]);
            }
        }
        __syncthreads();
    }

    int g = lane >> 2, c = lane & 3;
    #pragma unroll
    for (int mi = 0; mi < 4; mi++) {
        #pragma unroll
        for (int j = 0; j < 2; j++) {
            float* G = accg[mi][j];
            float* U = accu[mi][j];
            int col = n0 + nw * 16 + j * 8 + 2 * c;
            int r0 = m0 + mw * 64 + mi * 16 + g;
            float s0 = G[0] / (1.f + expf(-G[0])) * U[0];
            float s1 = G[1] / (1.f + expf(-G[1])) * U[1];
            float s2 = G[2] / (1.f + expf(-G[2])) * U[2];
            float s3 = G[3] / (1.f + expf(-G[3])) * U[3];
            *(__half2*)(C0 + (size_t)e * sCe + (size_t)r0 * ldc + col) = __floats2half2_rn(s0, s1);
            *(__half2*)(C0 + (size_t)e * sCe + (size_t)(r0 + 8) * ldc + col) = __floats2half2_rn(s2, s3);
        }
    }
}

// ---------------- Plain GEMM: A fp16, B fp32 (in-kernel cvt), templated out ----------------
template <typename OutT>
__global__ __launch_bounds__(256, 2)
void gemm2_mma(const __half* __restrict__ A0, int lda, size_t sAe,
               const float* __restrict__ B0, int ldb, size_t sBe,
               OutT* __restrict__ C0, int ldc, size_t sCe,
               int Kdim, const int* __restrict__ cnt)
{
    __shared__ __align__(16) __half As[2 * ABUF];
    __shared__ __align__(16) __half Bs[2 * BBUF];

    int e = blockIdx.z;
    int m0 = blockIdx.y * 128;
    if (cnt && m0 >= cnt[e]) return;
    int n0 = blockIdx.x * 128;

    int tid = threadIdx.x;
    int warp = tid >> 5, lane = tid & 31;
    int mw = warp & 1, nw = warp >> 1;

    const __half* A = A0 + (size_t)e * sAe + (size_t)m0 * lda;
    const float*  B = B0 + (size_t)e * sBe;
    uint32_t AsU = s2u(As), BsU = s2u(Bs);

    int ar = tid >> 1, acol = (tid & 1) * 16;
    int br = tid >> 3, sg = tid & 7;
    const __half* Ag = A + (size_t)ar * lda + acol;
    const float*  Bg = B + (size_t)br * ldb + n0 + sg * 16;

    float acc[4][4][4] = {};
    uint4 ra[2]; uint2 rbh[4];

    auto ldg = [&](int k0) {
        const uint4* ap = (const uint4*)(Ag + k0);
        ra[0] = ap[0]; ra[1] = ap[1];
        const float4* bp = (const float4*)(Bg + (size_t)k0 * ldb);
        rbh[0] = f4h(bp[0]); rbh[1] = f4h(bp[1]); rbh[2] = f4h(bp[2]); rbh[3] = f4h(bp[3]);
    };
    auto sts = [&](int b) {
        uint4* ad = (uint4*)(As + b * ABUF + ar * LDA_S + acol);
        ad[0] = ra[0]; ad[1] = ra[1];
        uint4* bd = (uint4*)(Bs + b * BBUF + br * LDB_S + sg * 16);
        bd[0] = make_uint4(rbh[0].x, rbh[0].y, rbh[1].x, rbh[1].y);
        bd[1] = make_uint4(rbh[2].x, rbh[2].y, rbh[3].x, rbh[3].y);
    };

    int NC = Kdim / 32;
    ldg(0);
    for (int i = 0; i < NC; i++) {
        int b = i & 1;
        sts(b);
        __syncthreads();
        if (i + 1 < NC) ldg((i + 1) * 32);

        uint32_t ab = AsU + (uint32_t)(b * ABUF) * 2;
        uint32_t bb = BsU + (uint32_t)(b * BBUF) * 2;
        #pragma unroll
        for (int ks = 0; ks < 32; ks += 16) {
            uint32_t af[4][4];
            #pragma unroll
            for (int mi = 0; mi < 4; mi++) {
                int r = mw * 64 + mi * 16 + (lane & 15);
                LDSM4(af[mi], ab + (uint32_t)(r * LDA_S + ks + (lane >> 4) * 8) * 2);
            }
            uint32_t bf0[4], bf1[4];
            int kr = ks + (lane & 15);
            LDSM4T(bf0, bb + (uint32_t)(kr * LDB_S + nw * 32 + (lane >> 4) * 8) * 2);
            LDSM4T(bf1, bb + (uint32_t)(kr * LDB_S + nw * 32 + 16 + (lane >> 4) * 8) * 2);
            #pragma unroll
            for (int mi = 0; mi < 4; mi++) {
                MMA16816(acc[mi][0], af[mi], bf0[0], bf0[1]);
                MMA16816(acc[mi][1], af[mi], bf0[2], bf0[3]);
                MMA16816(acc[mi][2], af[mi], bf1[0], bf1[1]);
                MMA16816(acc[mi][3], af[mi], bf1[2], bf1[3]);
            }
        }
        __syncthreads();
    }

    int g = lane >> 2, c = lane & 3;
    #pragma unroll
    for (int mi = 0; mi < 4; mi++) {
        #pragma unroll
        for (int j = 0; j < 4; j++) {
            float* D = acc[mi][j];
            int col = n0 + nw * 32 + j * 8 + 2 * c;
            int r0 = m0 + mw * 64 + mi * 16 + g;
            OutT* Cb = C0 + (size_t)e * sCe;
            if constexpr (sizeof(OutT) == 4) {
                *(float2*)((float*)Cb + (size_t)r0 * ldc + col) = make_float2(D[0], D[1]);
                *(float2*)((float*)Cb + (size_t)(r0 + 8) * ldc + col) = make_float2(D[2], D[3]);
            } else {
                *(__half2*)((__half*)Cb + (size_t)r0 * ldc + col) = __floats2half2_rn(D[0], D[1]);
                *(__half2*)((__half*)Cb + (size_t)(r0 + 8) * ldc + col) = __floats2half2_rn(D[2], D[3]);
            }
        }
    }
}

// ---------------- Combine (eo fp16) ----------------
__global__ void combine_kernel(float* __restrict__ out) {
    int t = blockIdx.x;
    int h = threadIdx.x;
    int ids[TOPK], pos[TOPK]; float w[TOPK];
    #pragma unroll
    for (int k = 0; k < TOPK; k++) {
        ids[k] = g_ids[t * TOPK + k];
        pos[k] = g_pos[t * TOPK + k];
        w[k]   = g_wts[t * TOPK + k];
    }
    float4* o4 = (float4*)(out + (size_t)t * HDIM);
    float4 acc = o4[h];
    #pragma unroll
    for (int k = 0; k < TOPK; k++) {
        if (pos[k] < CAP) {
            const uint2* v2 = (const uint2*)(g_eo16 + ((size_t)ids[k] * CAP + pos[k]) * HDIM);
            uint2 u = v2[h];
            float2 fa = __half22float2(*(__half2*)&u.x);
            float2 fb = __half22float2(*(__half2*)&u.y);
            acc.x = fmaf(w[k], fa.x, acc.x);
            acc.y = fmaf(w[k], fa.y, acc.y);
            acc.z = fmaf(w[k], fb.x, acc.z);
            acc.w = fmaf(w[k], fb.y, acc.w);
        }
    }
    o4[h] = acc;
}

// ---------------- Launch ----------------
extern "C" void kernel_launch(void* const* d_in, const int* in_sizes, int n_in,
                              void* d_out, int out_size)
{
    const float* x      = (const float*)d_in[0];
    const float* gate_w = (const float*)d_in[1];
    const float* bias   = (const float*)d_in[2];
    const float* w13    = (const float*)d_in[3];
    const float* w2     = (const float*)d_in[4];
    const float* sw13   = (const float*)d_in[5];
    const float* sw2    = (const float*)d_in[6];
    float* out = (float*)d_out;

    __half *buf16, *act16, *eo16, *x16, *acts16;
    int* cnt;
    cudaGetSymbolAddress((void**)&buf16,  g_buf16);
    cudaGetSymbolAddress((void**)&act16,  g_act16);
    cudaGetSymbolAddress((void**)&eo16,   g_eo16);
    cudaGetSymbolAddress((void**)&x16,    g_x16);
    cudaGetSymbolAddress((void**)&acts16, g_acts16);
    cudaGetSymbolAddress((void**)&cnt,    g_cnt);

    static cudaStream_t s2 = nullptr;
    static cudaEvent_t evA = nullptr, evSh = nullptr;
    if (!s2) {
        cudaStreamCreateWithFlags(&s2, cudaStreamNonBlocking);
        cudaEventCreateWithFlags(&evA,  cudaEventDisableTiming);
        cudaEventCreateWithFlags(&evSh, cudaEventDisableTiming);
    }

    // fork
    cudaEventRecord(evA, 0);
    cudaStreamWaitEvent(s2, evA, 0);

    // ---- side stream: shared-expert chain ----
    conv16_kernel<<<(T_TOK * HDIM / 4 + 255) / 256, 256, 0, s2>>>(x, x16, T_TOK * HDIM / 4);
    gemm13_mma<<<dim3(FSH / 64, T_TOK / 128, 1), 256, 0, s2>>>(
        x16, HDIM, 0, sw13, 2 * FSH, 0, FSH, acts16, FSH, 0, HDIM, nullptr);
    gemm2_mma<float><<<dim3(HDIM / 128, T_TOK / 128, 1), 256, 0, s2>>>(
        acts16, FSH, 0, sw2, HDIM, 0, out, HDIM, 0, FSH, nullptr);
    cudaEventRecord(evSh, s2);

    // ---- main stream: routing + routed experts ----
    gate_topk_kernel<<<T_TOK, 64>>>(x, gate_w, bias);
    zero_cnt_kernel<<<1, 64>>>();
    assign_kernel<<<(T_TOK * TOPK + 255) / 256, 256>>>();
    scatter16_kernel<<<T_TOK * TOPK, 128>>>(x);

    gemm13_mma<<<dim3(FDIM / 64, CAP / 128, NEXP), 256>>>(
        buf16, HDIM, (size_t)CAP * HDIM,
        w13, 2 * FDIM, (size_t)HDIM * 2 * FDIM, FDIM,
        act16, FDIM, (size_t)CAP * FDIM,
        HDIM, cnt);

    gemm2_mma<__half><<<dim3(HDIM / 128, CAP / 128, NEXP), 256>>>(
        act16, FDIM, (size_t)CAP * FDIM,
        w2, HDIM, (size_t)FDIM * HDIM,
        eo16, HDIM, (size_t)CAP * HDIM,
        FDIM, cnt);

    // join shared branch, then combine
    cudaStreamWaitEvent(0, evSh, 0);
    combine_kernel<<<T_TOK, 256>>>(out);
}

// round 6
// speedup vs baseline: 1.9567x; 1.7059x over previous
#include <cuda_runtime.h>
#include <cuda_fp16.h>
#include <cstdint>
#include <math.h>

// ---------------- Problem constants ----------------
#define T_TOK   1024
#define HDIM    1024
#define NEXP    64
#define TOPK    6
#define NGRP    8
#define TOPG    4
#define FDIM    512
#define FSH     1024
#define CAP     384
#define SCALE   2.5f

// ---------------- Device scratch ----------------
__device__ __align__(16) __half g_buf16 [(size_t)NEXP * CAP * HDIM];      // dispatch [E,CAP,H]
__device__ __align__(16) __half g_act16 [(size_t)NEXP * CAP * FDIM];      // act [E,CAP,F]
__device__ __align__(16) __half g_eo16  [(size_t)NEXP * CAP * HDIM];      // expert out fp16
__device__ __align__(16) __half g_x16   [(size_t)T_TOK * HDIM];
__device__ __align__(16) __half g_acts16[(size_t)T_TOK * FSH];
__device__ __align__(16) float  g_logits[(size_t)T_TOK * NEXP];
__device__ int   g_cnt[NEXP];
__device__ int   g_ids[T_TOK * TOPK];
__device__ int   g_pos[T_TOK * TOPK];
__device__ float g_wts[T_TOK * TOPK];

// ---------------- PTX helpers ----------------
static __device__ __forceinline__ uint32_t s2u(const void* p) {
    uint32_t a;
    asm("{ .reg .u64 t; cvta.to.shared.u64 t, %1; cvt.u32.u64 %0, t; }" : "=r"(a) : "l"(p));
    return a;
}
#define LDSM4(r, addr) \
    asm volatile("ldmatrix.sync.aligned.m8n8.x4.shared.b16 {%0,%1,%2,%3}, [%4];" \
        : "=r"((r)[0]), "=r"((r)[1]), "=r"((r)[2]), "=r"((r)[3]) : "r"(addr))
#define LDSM4T(r, addr) \
    asm volatile("ldmatrix.sync.aligned.m8n8.x4.trans.shared.b16 {%0,%1,%2,%3}, [%4];" \
        : "=r"((r)[0]), "=r"((r)[1]), "=r"((r)[2]), "=r"((r)[3]) : "r"(addr))
#define MMA16816(d, a, b0, b1) \
    asm volatile("mma.sync.aligned.m16n8k16.row.col.f32.f16.f16.f32 " \
        "{%0,%1,%2,%3}, {%4,%5,%6,%7}, {%8,%9}, {%0,%1,%2,%3};" \
        : "+f"((d)[0]), "+f"((d)[1]), "+f"((d)[2]), "+f"((d)[3]) \
        : "r"((a)[0]), "r"((a)[1]), "r"((a)[2]), "r"((a)[3]), "r"(b0), "r"(b1))

// SMEM tile geometry (halves)
#define LDA_S 40     // 32 k + 8 pad
#define LDB_S 136    // 128 n + 8 pad
#define ABUF  (128 * LDA_S)
#define BBUF  (32 * LDB_S)

// ---------------- Gate logits: fp32 tiled GEMM, 16 tokens x 64 experts / block ----------------
// Accumulation order per output: sequential fmaf over k = 0..1023 (matches prior passing version).
__global__ __launch_bounds__(256)
void gate_logits_kernel(const float* __restrict__ x, const float* __restrict__ gw,
                        float* __restrict__ logits)
{
    __shared__ float xs[16][65];
    __shared__ float gws[64][65];
    int m0 = blockIdx.x * 16;
    int tid = threadIdx.x;
    int m = tid & 15, n4 = tid >> 4;          // outputs (m, n4*4 + j)
    float acc[4] = {};

    for (int k0 = 0; k0 < HDIM; k0 += 64) {
        {
            int r = tid >> 4, c = (tid & 15) * 4;
            float4 v = *(const float4*)(x + (size_t)(m0 + r) * HDIM + k0 + c);
            xs[r][c] = v.x; xs[r][c + 1] = v.y; xs[r][c + 2] = v.z; xs[r][c + 3] = v.w;
        }
        #pragma unroll
        for (int i = 0; i < 4; i++) {
            int idx = tid + i * 256;          // 1024 quads
            int r = idx >> 4, c = (idx & 15) * 4;
            float4 v = *(const float4*)(gw + (size_t)r * HDIM + k0 + c);
            gws[r][c] = v.x; gws[r][c + 1] = v.y; gws[r][c + 2] = v.z; gws[r][c + 3] = v.w;
        }
        __syncthreads();
        #pragma unroll 8
        for (int k = 0; k < 64; k++) {
            float a = xs[m][k];
            acc[0] = fmaf(a, gws[n4 * 4 + 0][k], acc[0]);
            acc[1] = fmaf(a, gws[n4 * 4 + 1][k], acc[1]);
            acc[2] = fmaf(a, gws[n4 * 4 + 2][k], acc[2]);
            acc[3] = fmaf(a, gws[n4 * 4 + 3][k], acc[3]);
        }
        __syncthreads();
    }
    #pragma unroll
    for (int j = 0; j < 4; j++)
        logits[(size_t)(m0 + m) * NEXP + n4 * 4 + j] = acc[j];
}

// ---------------- Top-k selection: 4 tokens / 256-thread block ----------------
__global__ __launch_bounds__(256)
void topk_kernel(const float* __restrict__ logits, const float* __restrict__ bias)
{
    __shared__ float scores[4][NEXP];
    __shared__ float sc[4][NEXP];
    int tid = threadIdx.x;
    int tk = tid >> 6, tl = tid & 63;
    int t = blockIdx.x * 4 + tk;

    float lg = logits[(size_t)t * NEXP + tl];
    float s = 1.f / (1.f + expf(-lg));
    scores[tk][tl] = s;
    sc[tk][tl] = s + bias[tl];
    __syncthreads();

    if (tl == 0) {
        float gs[NGRP];
        for (int gi = 0; gi < NGRP; gi++) {
            float m1 = -1e30f, m2 = -1e30f;
            for (int j = 0; j < 8; j++) {
                float v = sc[tk][gi * 8 + j];
                if (v > m1) { m2 = m1; m1 = v; } else if (v > m2) m2 = v;
            }
            gs[gi] = m1 + m2;
        }
        bool gsel[NGRP];
        for (int gi = 0; gi < NGRP; gi++) gsel[gi] = false;
        for (int r = 0; r < TOPG; r++) {
            int bi = -1; float bv = -1e30f;
            for (int gi = 0; gi < NGRP; gi++)
                if (!gsel[gi] && gs[gi] > bv) { bv = gs[gi]; bi = gi; }
            gsel[bi] = true;
        }
        float masked[NEXP];
        for (int i = 0; i < NEXP; i++) masked[i] = gsel[i >> 3] ? sc[tk][i] : -1e30f;
        int id[TOPK]; float wsum = 0.f;
        for (int r = 0; r < TOPK; r++) {
            int bi = -1; float bv = -1e30f;
            for (int i = 0; i < NEXP; i++)
                if (masked[i] > bv) { bv = masked[i]; bi = i; }
            masked[bi] = -1e30f;
            id[r] = bi;
            wsum += scores[tk][bi];
        }
        float inv = SCALE / wsum;
        for (int r = 0; r < TOPK; r++) {
            g_ids[t * TOPK + r] = id[r];
            g_wts[t * TOPK + r] = scores[tk][id[r]] * inv;
        }
    }
}

__global__ void zero_cnt_kernel() { if (threadIdx.x < NEXP) g_cnt[threadIdx.x] = 0; }

__global__ void assign_kernel() {
    int i = blockIdx.x * blockDim.x + threadIdx.x;
    if (i < T_TOK * TOPK) g_pos[i] = atomicAdd(&g_cnt[g_ids[i]], 1);
}

__global__ void scatter16_kernel(const float* __restrict__ x) {
    int i = blockIdx.x;
    int p = g_pos[i];
    if (p >= CAP) return;
    int e = g_ids[i];
    int t = i / TOPK;
    const float4* src = (const float4*)(x + (size_t)t * HDIM);
    __half* dst = g_buf16 + ((size_t)e * CAP + p) * HDIM;
    for (int j = threadIdx.x; j < HDIM / 4; j += blockDim.x) {
        float4 v = src[j];
        __half2 a = __floats2half2_rn(v.x, v.y);
        __half2 b = __floats2half2_rn(v.z, v.w);
        uint2 u = make_uint2(*(uint32_t*)&a, *(uint32_t*)&b);
        *(uint2*)(dst + j * 4) = u;
    }
}

__global__ void conv16_kernel(const float* __restrict__ in, __half* __restrict__ out, int n4) {
    int i = blockIdx.x * blockDim.x + threadIdx.x;
    if (i < n4) {
        float4 v = ((const float4*)in)[i];
        __half2 a = __floats2half2_rn(v.x, v.y);
        __half2 b = __floats2half2_rn(v.z, v.w);
        uint2 u = make_uint2(*(uint32_t*)&a, *(uint32_t*)&b);
        *(uint2*)(out + (size_t)i * 4) = u;
    }
}

// convert 4 fp32 (float4) -> uint2 of 4 halves
static __device__ __forceinline__ uint2 f4h(float4 v) {
    __half2 a = __floats2half2_rn(v.x, v.y);
    __half2 b = __floats2half2_rn(v.z, v.w);
    return make_uint2(*(uint32_t*)&a, *(uint32_t*)&b);
}

// ---------------- Fused up-proj + SiLU*Mul: A fp16, B fp32 (in-kernel cvt) ----------------
__global__ __launch_bounds__(256, 2)
void gemm13_mma(const __half* __restrict__ A0, int lda, size_t sAe,
                const float* __restrict__ B0, int ldb, size_t sBe, int halfOff,
                __half* __restrict__ C0, int ldc, size_t sCe,
                int Kdim, const int* __restrict__ cnt)
{
    __shared__ __align__(16) __half As[2 * ABUF];
    __shared__ __align__(16) __half Bs[2 * BBUF];

    int e = blockIdx.z;
    int m0 = blockIdx.y * 128;
    if (cnt && m0 >= cnt[e]) return;
    int n0 = blockIdx.x * 64;

    int tid = threadIdx.x;
    int warp = tid >> 5, lane = tid & 31;
    int mw = warp & 1, nw = warp >> 1;

    const __half* A = A0 + (size_t)e * sAe + (size_t)m0 * lda;
    const float*  B = B0 + (size_t)e * sBe;
    uint32_t AsU = s2u(As), BsU = s2u(Bs);

    int ar = tid >> 1, acol = (tid & 1) * 16;
    int br = tid >> 3, sg = tid & 7;
    int bcolg = (sg < 4) ? (n0 + sg * 16) : (halfOff + n0 + (sg - 4) * 16);
    int bcols = (sg < 4) ? (sg * 16) : (64 + (sg - 4) * 16);
    const __half* Ag = A + (size_t)ar * lda + acol;
    const float*  Bg = B + (size_t)br * ldb + bcolg;

    float accg[4][2][4] = {}, accu[4][2][4] = {};
    uint4 ra[2]; uint2 rbh[4];

    auto ldg = [&](int k0) {
        const uint4* ap = (const uint4*)(Ag + k0);
        ra[0] = ap[0]; ra[1] = ap[1];
        const float4* bp = (const float4*)(Bg + (size_t)k0 * ldb);
        rbh[0] = f4h(bp[0]); rbh[1] = f4h(bp[1]); rbh[2] = f4h(bp[2]); rbh[3] = f4h(bp[3]);
    };
    auto sts = [&](int b) {
        uint4* ad = (uint4*)(As + b * ABUF + ar * LDA_S + acol);
        ad[0] = ra[0]; ad[1] = ra[1];
        uint4* bd = (uint4*)(Bs + b * BBUF + br * LDB_S + bcols);
        bd[0] = make_uint4(rbh[0].x, rbh[0].y, rbh[1].x, rbh[1].y);
        bd[1] = make_uint4(rbh[2].x, rbh[2].y, rbh[3].x, rbh[3].y);
    };

    int NC = Kdim / 32;
    ldg(0);
    for (int i = 0; i < NC; i++) {
        int b = i & 1;
        sts(b);
        __syncthreads();
        if (i + 1 < NC) ldg((i + 1) * 32);

        uint32_t ab = AsU + (uint32_t)(b * ABUF) * 2;
        uint32_t bb = BsU + (uint32_t)(b * BBUF) * 2;
        #pragma unroll
        for (int ks = 0; ks < 32; ks += 16) {
            uint32_t af[4][4];
            #pragma unroll
            for (int mi = 0; mi < 4; mi++) {
                int r = mw * 64 + mi * 16 + (lane & 15);
                LDSM4(af[mi], ab + (uint32_t)(r * LDA_S + ks + (lane >> 4) * 8) * 2);
            }
            uint32_t bgf[4], buf[4];
            int kr = ks + (lane & 15);
            LDSM4T(bgf, bb + (uint32_t)(kr * LDB_S + nw * 16 + (lane >> 4) * 8) * 2);
            LDSM4T(buf, bb + (uint32_t)(kr * LDB_S + 64 + nw * 16 + (lane >> 4) * 8) * 2);
            #pragma unroll
            for (int mi = 0; mi < 4; mi++) {
                MMA16816(accg[mi][0], af[mi], bgf[0], bgf[1]);
                MMA16816(accg[mi][1], af[mi], bgf[2], bgf[3]);
                MMA16816(accu[mi][0], af[mi], buf[0], buf[1]);
                MMA16816(accu[mi][1], af[mi], buf[2], buf[3]);
            }
        }
        __syncthreads();
    }

    int g = lane >> 2, c = lane & 3;
    #pragma unroll
    for (int mi = 0; mi < 4; mi++) {
        #pragma unroll
        for (int j = 0; j < 2; j++) {
            float* G = accg[mi][j];
            float* U = accu[mi][j];
            int col = n0 + nw * 16 + j * 8 + 2 * c;
            int r0 = m0 + mw * 64 + mi * 16 + g;
            float s0 = G[0] / (1.f + expf(-G[0])) * U[0];
            float s1 = G[1] / (1.f + expf(-G[1])) * U[1];
            float s2 = G[2] / (1.f + expf(-G[2])) * U[2];
            float s3 = G[3] / (1.f + expf(-G[3])) * U[3];
            *(__half2*)(C0 + (size_t)e * sCe + (size_t)r0 * ldc + col) = __floats2half2_rn(s0, s1);
            *(__half2*)(C0 + (size_t)e * sCe + (size_t)(r0 + 8) * ldc + col) = __floats2half2_rn(s2, s3);
        }
    }
}

// ---------------- Plain GEMM: A fp16, B fp32 (in-kernel cvt), templated out ----------------
template <typename OutT>
__global__ __launch_bounds__(256, 2)
void gemm2_mma(const __half* __restrict__ A0, int lda, size_t sAe,
               const float* __restrict__ B0, int ldb, size_t sBe,
               OutT* __restrict__ C0, int ldc, size_t sCe,
               int Kdim, const int* __restrict__ cnt)
{
    __shared__ __align__(16) __half As[2 * ABUF];
    __shared__ __align__(16) __half Bs[2 * BBUF];

    int e = blockIdx.z;
    int m0 = blockIdx.y * 128;
    if (cnt && m0 >= cnt[e]) return;
    int n0 = blockIdx.x * 128;

    int tid = threadIdx.x;
    int warp = tid >> 5, lane = tid & 31;
    int mw = warp & 1, nw = warp >> 1;

    const __half* A = A0 + (size_t)e * sAe + (size_t)m0 * lda;
    const float*  B = B0 + (size_t)e * sBe;
    uint32_t AsU = s2u(As), BsU = s2u(Bs);

    int ar = tid >> 1, acol = (tid & 1) * 16;
    int br = tid >> 3, sg = tid & 7;
    const __half* Ag = A + (size_t)ar * lda + acol;
    const float*  Bg = B + (size_t)br * ldb + n0 + sg * 16;

    float acc[4][4][4] = {};
    uint4 ra[2]; uint2 rbh[4];

    auto ldg = [&](int k0) {
        const uint4* ap = (const uint4*)(Ag + k0);
        ra[0] = ap[0]; ra[1] = ap[1];
        const float4* bp = (const float4*)(Bg + (size_t)k0 * ldb);
        rbh[0] = f4h(bp[0]); rbh[1] = f4h(bp[1]); rbh[2] = f4h(bp[2]); rbh[3] = f4h(bp[3]);
    };
    auto sts = [&](int b) {
        uint4* ad = (uint4*)(As + b * ABUF + ar * LDA_S + acol);
        ad[0] = ra[0]; ad[1] = ra[1];
        uint4* bd = (uint4*)(Bs + b * BBUF + br * LDB_S + sg * 16);
        bd[0] = make_uint4(rbh[0].x, rbh[0].y, rbh[1].x, rbh[1].y);
        bd[1] = make_uint4(rbh[2].x, rbh[2].y, rbh[3].x, rbh[3].y);
    };

    int NC = Kdim / 32;
    ldg(0);
    for (int i = 0; i < NC; i++) {
        int b = i & 1;
        sts(b);
        __syncthreads();
        if (i + 1 < NC) ldg((i + 1) * 32);

        uint32_t ab = AsU + (uint32_t)(b * ABUF) * 2;
        uint32_t bb = BsU + (uint32_t)(b * BBUF) * 2;
        #pragma unroll
        for (int ks = 0; ks < 32; ks += 16) {
            uint32_t af[4][4];
            #pragma unroll
            for (int mi = 0; mi < 4; mi++) {
                int r = mw * 64 + mi * 16 + (lane & 15);
                LDSM4(af[mi], ab + (uint32_t)(r * LDA_S + ks + (lane >> 4) * 8) * 2);
            }
            uint32_t bf0[4], bf1[4];
            int kr = ks + (lane & 15);
            LDSM4T(bf0, bb + (uint32_t)(kr * LDB_S + nw * 32 + (lane >> 4) * 8) * 2);
            LDSM4T(bf1, bb + (uint32_t)(kr * LDB_S + nw * 32 + 16 + (lane >> 4) * 8) * 2);
            #pragma unroll
            for (int mi = 0; mi < 4; mi++) {
                MMA16816(acc[mi][0], af[mi], bf0[0], bf0[1]);
                MMA16816(acc[mi][1], af[mi], bf0[2], bf0[3]);
                MMA16816(acc[mi][2], af[mi], bf1[0], bf1[1]);
                MMA16816(acc[mi][3], af[mi], bf1[2], bf1[3]);
            }
        }
        __syncthreads();
    }

    int g = lane >> 2, c = lane & 3;
    #pragma unroll
    for (int mi = 0; mi < 4; mi++) {
        #pragma unroll
        for (int j = 0; j < 4; j++) {
            float* D = acc[mi][j];
            int col = n0 + nw * 32 + j * 8 + 2 * c;
            int r0 = m0 + mw * 64 + mi * 16 + g;
            OutT* Cb = C0 + (size_t)e * sCe;
            if constexpr (sizeof(OutT) == 4) {
                *(float2*)((float*)Cb + (size_t)r0 * ldc + col) = make_float2(D[0], D[1]);
                *(float2*)((float*)Cb + (size_t)(r0 + 8) * ldc + col) = make_float2(D[2], D[3]);
            } else {
                *(__half2*)((__half*)Cb + (size_t)r0 * ldc + col) = __floats2half2_rn(D[0], D[1]);
                *(__half2*)((__half*)Cb + (size_t)(r0 + 8) * ldc + col) = __floats2half2_rn(D[2], D[3]);
            }
        }
    }
}

// ---------------- Combine (eo fp16) ----------------
__global__ void combine_kernel(float* __restrict__ out) {
    int t = blockIdx.x;
    int h = threadIdx.x;
    int ids[TOPK], pos[TOPK]; float w[TOPK];
    #pragma unroll
    for (int k = 0; k < TOPK; k++) {
        ids[k] = g_ids[t * TOPK + k];
        pos[k] = g_pos[t * TOPK + k];
        w[k]   = g_wts[t * TOPK + k];
    }
    float4* o4 = (float4*)(out + (size_t)t * HDIM);
    float4 acc = o4[h];
    #pragma unroll
    for (int k = 0; k < TOPK; k++) {
        if (pos[k] < CAP) {
            const uint2* v2 = (const uint2*)(g_eo16 + ((size_t)ids[k] * CAP + pos[k]) * HDIM);
            uint2 u = v2[h];
            float2 fa = __half22float2(*(__half2*)&u.x);
            float2 fb = __half22float2(*(__half2*)&u.y);
            acc.x = fmaf(w[k], fa.x, acc.x);
            acc.y = fmaf(w[k], fa.y, acc.y);
            acc.z = fmaf(w[k], fb.x, acc.z);
            acc.w = fmaf(w[k], fb.y, acc.w);
        }
    }
    o4[h] = acc;
}

// ---------------- Launch ----------------
extern "C" void kernel_launch(void* const* d_in, const int* in_sizes, int n_in,
                              void* d_out, int out_size)
{
    const float* x      = (const float*)d_in[0];
    const float* gate_w = (const float*)d_in[1];
    const float* bias   = (const float*)d_in[2];
    const float* w13    = (const float*)d_in[3];
    const float* w2     = (const float*)d_in[4];
    const float* sw13   = (const float*)d_in[5];
    const float* sw2    = (const float*)d_in[6];
    float* out = (float*)d_out;

    __half *buf16, *act16, *eo16, *x16, *acts16;
    float* logits; int* cnt;
    cudaGetSymbolAddress((void**)&buf16,  g_buf16);
    cudaGetSymbolAddress((void**)&act16,  g_act16);
    cudaGetSymbolAddress((void**)&eo16,   g_eo16);
    cudaGetSymbolAddress((void**)&x16,    g_x16);
    cudaGetSymbolAddress((void**)&acts16, g_acts16);
    cudaGetSymbolAddress((void**)&logits, g_logits);
    cudaGetSymbolAddress((void**)&cnt,    g_cnt);

    static cudaStream_t s2 = nullptr;
    static cudaEvent_t evA = nullptr, evSh = nullptr;
    if (!s2) {
        cudaStreamCreateWithFlags(&s2, cudaStreamNonBlocking);
        cudaEventCreateWithFlags(&evA,  cudaEventDisableTiming);
        cudaEventCreateWithFlags(&evSh, cudaEventDisableTiming);
    }

    // fork
    cudaEventRecord(evA, 0);
    cudaStreamWaitEvent(s2, evA, 0);

    // ---- side stream: shared-expert chain ----
    conv16_kernel<<<(T_TOK * HDIM / 4 + 255) / 256, 256, 0, s2>>>(x, x16, T_TOK * HDIM / 4);
    gemm13_mma<<<dim3(FSH / 64, T_TOK / 128, 1), 256, 0, s2>>>(
        x16, HDIM, 0, sw13, 2 * FSH, 0, FSH, acts16, FSH, 0, HDIM, nullptr);
    gemm2_mma<float><<<dim3(HDIM / 128, T_TOK / 128, 1), 256, 0, s2>>>(
        acts16, FSH, 0, sw2, HDIM, 0, out, HDIM, 0, FSH, nullptr);
    cudaEventRecord(evSh, s2);

    // ---- main stream: routing + routed experts ----
    gate_logits_kernel<<<T_TOK / 16, 256>>>(x, gate_w, logits);
    topk_kernel<<<T_TOK / 4, 256>>>(logits, bias);
    zero_cnt_kernel<<<1, 64>>>();
    assign_kernel<<<(T_TOK * TOPK + 255) / 256, 256>>>();
    scatter16_kernel<<<T_TOK * TOPK, 128>>>(x);

    gemm13_mma<<<dim3(FDIM / 64, CAP / 128, NEXP), 256>>>(
        buf16, HDIM, (size_t)CAP * HDIM,
        w13, 2 * FDIM, (size_t)HDIM * 2 * FDIM, FDIM,
        act16, FDIM, (size_t)CAP * FDIM,
        HDIM, cnt);

    gemm2_mma<__half><<<dim3(HDIM / 128, CAP / 128, NEXP), 256>>>(
        act16, FDIM, (size_t)CAP * FDIM,
        w2, HDIM, (size_t)FDIM * HDIM,
        eo16, HDIM, (size_t)CAP * HDIM,
        FDIM, cnt);

    // join shared branch, then combine
    cudaStreamWaitEvent(0, evSh, 0);
    combine_kernel<<<T_TOK, 256>>>(out);
}

// round 7
// speedup vs baseline: 2.2825x; 1.1665x over previous
#include <cuda_runtime.h>
#include <cuda_fp16.h>
#include <cstdint>
#include <math.h>

// ---------------- Problem constants ----------------
#define T_TOK   1024
#define HDIM    1024
#define NEXP    64
#define TOPK    6
#define NGRP    8
#define TOPG    4
#define FDIM    512
#define FSH     1024
#define CAP     384
#define SCALE   2.5f
#define KSPLIT  8
#define KSEG    (HDIM / KSPLIT)   // 128

// ---------------- Device scratch ----------------
__device__ __align__(16) __half g_buf16 [(size_t)NEXP * CAP * HDIM];
__device__ __align__(16) __half g_act16 [(size_t)NEXP * CAP * FDIM];
__device__ __align__(16) __half g_eo16  [(size_t)NEXP * CAP * HDIM];
__device__ __align__(16) __half g_x16   [(size_t)T_TOK * HDIM];
__device__ __align__(16) __half g_acts16[(size_t)T_TOK * FSH];
__device__ __align__(16) float  g_logP  [(size_t)KSPLIT * T_TOK * NEXP];
__device__ int   g_cnt[NEXP];
__device__ int   g_ids[T_TOK * TOPK];
__device__ int   g_pos[T_TOK * TOPK];
__device__ float g_wts[T_TOK * TOPK];

// ---------------- PTX helpers ----------------
static __device__ __forceinline__ uint32_t s2u(const void* p) {
    uint32_t a;
    asm("{ .reg .u64 t; cvta.to.shared.u64 t, %1; cvt.u32.u64 %0, t; }" : "=r"(a) : "l"(p));
    return a;
}
#define CPA16(dst, src) asm volatile("cp.async.cg.shared.global [%0], [%1], 16;" :: "r"(dst), "l"(src))
#define CP_COMMIT()     asm volatile("cp.async.commit_group;")
#define CP_WAIT1()      asm volatile("cp.async.wait_group 1;")
#define CP_WAIT0()      asm volatile("cp.async.wait_group 0;")
#define LDSM4(r, addr) \
    asm volatile("ldmatrix.sync.aligned.m8n8.x4.shared.b16 {%0,%1,%2,%3}, [%4];" \
        : "=r"((r)[0]), "=r"((r)[1]), "=r"((r)[2]), "=r"((r)[3]) : "r"(addr))
#define LDSM4T(r, addr) \
    asm volatile("ldmatrix.sync.aligned.m8n8.x4.trans.shared.b16 {%0,%1,%2,%3}, [%4];" \
        : "=r"((r)[0]), "=r"((r)[1]), "=r"((r)[2]), "=r"((r)[3]) : "r"(addr))
#define MMA16816(d, a, b0, b1) \
    asm volatile("mma.sync.aligned.m16n8k16.row.col.f32.f16.f16.f32 " \
        "{%0,%1,%2,%3}, {%4,%5,%6,%7}, {%8,%9}, {%0,%1,%2,%3};" \
        : "+f"((d)[0]), "+f"((d)[1]), "+f"((d)[2]), "+f"((d)[3]) \
        : "r"((a)[0]), "r"((a)[1]), "r"((a)[2]), "r"((a)[3]), "r"(b0), "r"(b1))

// SMEM tile geometry (halves)
#define LDA_S 40
#define LDB_S 136
#define ABUF  (128 * LDA_S)
#define BBUF  (32 * LDB_S)

// ---------------- Gate logits: split-K fp32 GEMM ----------------
// block = (token-tile of 16) x (K segment of 128); partial accumulation sequential within segment.
__global__ __launch_bounds__(256)
void gate_logits_kernel(const float* __restrict__ x, const float* __restrict__ gw,
                        float* __restrict__ logP)
{
    __shared__ float xs[16][65];
    __shared__ float gws[64][65];
    int m0 = blockIdx.x * 16;
    int kb = blockIdx.y * KSEG;
    int tid = threadIdx.x;
    int m = tid & 15, n4 = tid >> 4;
    float acc[4] = {};

    for (int k0 = kb; k0 < kb + KSEG; k0 += 64) {
        {
            int r = tid >> 4, c = (tid & 15) * 4;
            float4 v = *(const float4*)(x + (size_t)(m0 + r) * HDIM + k0 + c);
            xs[r][c] = v.x; xs[r][c + 1] = v.y; xs[r][c + 2] = v.z; xs[r][c + 3] = v.w;
        }
        #pragma unroll
        for (int i = 0; i < 4; i++) {
            int idx = tid + i * 256;
            int r = idx >> 4, c = (idx & 15) * 4;
            float4 v = *(const float4*)(gw + (size_t)r * HDIM + k0 + c);
            gws[r][c] = v.x; gws[r][c + 1] = v.y; gws[r][c + 2] = v.z; gws[r][c + 3] = v.w;
        }
        __syncthreads();
        #pragma unroll 8
        for (int k = 0; k < 64; k++) {
            float a = xs[m][k];
            acc[0] = fmaf(a, gws[n4 * 4 + 0][k], acc[0]);
            acc[1] = fmaf(a, gws[n4 * 4 + 1][k], acc[1]);
            acc[2] = fmaf(a, gws[n4 * 4 + 2][k], acc[2]);
            acc[3] = fmaf(a, gws[n4 * 4 + 3][k], acc[3]);
        }
        __syncthreads();
    }
    float* dst = logP + ((size_t)blockIdx.y * T_TOK + m0 + m) * NEXP + n4 * 4;
    #pragma unroll
    for (int j = 0; j < 4; j++) dst[j] = acc[j];
}

__global__ void zero_cnt_kernel() { if (threadIdx.x < NEXP) g_cnt[threadIdx.x] = 0; }

// ---------------- Top-k selection + slot assignment: 4 tokens / block ----------------
__global__ __launch_bounds__(256)
void topk_kernel(const float* __restrict__ logP, const float* __restrict__ bias)
{
    __shared__ float scores[4][NEXP];
    __shared__ float sc[4][NEXP];
    int tid = threadIdx.x;
    int tk = tid >> 6, tl = tid & 63;
    int t = blockIdx.x * 4 + tk;

    float lg = 0.f;
    #pragma unroll
    for (int ky = 0; ky < KSPLIT; ky++)
        lg += logP[((size_t)ky * T_TOK + t) * NEXP + tl];
    float s = 1.f / (1.f + expf(-lg));
    scores[tk][tl] = s;
    sc[tk][tl] = s + bias[tl];
    __syncthreads();

    if (tl == 0) {
        float gs[NGRP];
        for (int gi = 0; gi < NGRP; gi++) {
            float m1 = -1e30f, m2 = -1e30f;
            for (int j = 0; j < 8; j++) {
                float v = sc[tk][gi * 8 + j];
                if (v > m1) { m2 = m1; m1 = v; } else if (v > m2) m2 = v;
            }
            gs[gi] = m1 + m2;
        }
        bool gsel[NGRP];
        for (int gi = 0; gi < NGRP; gi++) gsel[gi] = false;
        for (int r = 0; r < TOPG; r++) {
            int bi = -1; float bv = -1e30f;
            for (int gi = 0; gi < NGRP; gi++)
                if (!gsel[gi] && gs[gi] > bv) { bv = gs[gi]; bi = gi; }
            gsel[bi] = true;
        }
        float masked[NEXP];
        for (int i = 0; i < NEXP; i++) masked[i] = gsel[i >> 3] ? sc[tk][i] : -1e30f;
        int id[TOPK]; float wsum = 0.f;
        for (int r = 0; r < TOPK; r++) {
            int bi = -1; float bv = -1e30f;
            for (int i = 0; i < NEXP; i++)
                if (masked[i] > bv) { bv = masked[i]; bi = i; }
            masked[bi] = -1e30f;
            id[r] = bi;
            wsum += scores[tk][bi];
        }
        float inv = SCALE / wsum;
        for (int r = 0; r < TOPK; r++) {
            g_ids[t * TOPK + r] = id[r];
            g_wts[t * TOPK + r] = scores[tk][id[r]] * inv;
            g_pos[t * TOPK + r] = atomicAdd(&g_cnt[id[r]], 1);
        }
    }
}

__global__ void scatter16_kernel(const float* __restrict__ x) {
    int i = blockIdx.x;
    int p = g_pos[i];
    if (p >= CAP) return;
    int e = g_ids[i];
    int t = i / TOPK;
    const float4* src = (const float4*)(x + (size_t)t * HDIM);
    __half* dst = g_buf16 + ((size_t)e * CAP + p) * HDIM;
    for (int j = threadIdx.x; j < HDIM / 4; j += blockDim.x) {
        float4 v = src[j];
        __half2 a = __floats2half2_rn(v.x, v.y);
        __half2 b = __floats2half2_rn(v.z, v.w);
        uint2 u = make_uint2(*(uint32_t*)&a, *(uint32_t*)&b);
        *(uint2*)(dst + j * 4) = u;
    }
}

__global__ void conv16_kernel(const float* __restrict__ in, __half* __restrict__ out, int n4) {
    int i = blockIdx.x * blockDim.x + threadIdx.x;
    if (i < n4) {
        float4 v = ((const float4*)in)[i];
        __half2 a = __floats2half2_rn(v.x, v.y);
        __half2 b = __floats2half2_rn(v.z, v.w);
        uint2 u = make_uint2(*(uint32_t*)&a, *(uint32_t*)&b);
        *(uint2*)(out + (size_t)i * 4) = u;
    }
}

static __device__ __forceinline__ uint2 f4h(float4 v) {
    __half2 a = __floats2half2_rn(v.x, v.y);
    __half2 b = __floats2half2_rn(v.z, v.w);
    return make_uint2(*(uint32_t*)&a, *(uint32_t*)&b);
}

// ---------------- Fused up-proj + SiLU*Mul: A fp16 (cp.async), B fp32 (reg cvt) ----------------
__global__ __launch_bounds__(256, 2)
void gemm13_mma(const __half* __restrict__ A0, int lda, size_t sAe,
                const float* __restrict__ B0, int ldb, size_t sBe, int halfOff,
                __half* __restrict__ C0, int ldc, size_t sCe,
                int Kdim, const int* __restrict__ cnt)
{
    __shared__ __align__(16) __half As[2 * ABUF];
    __shared__ __align__(16) __half Bs[2 * BBUF];

    int e = blockIdx.z;
    int m0 = blockIdx.y * 128;
    if (cnt && m0 >= cnt[e]) return;
    int n0 = blockIdx.x * 64;

    int tid = threadIdx.x;
    int warp = tid >> 5, lane = tid & 31;
    int mw = warp & 1, nw = warp >> 1;

    const __half* A = A0 + (size_t)e * sAe + (size_t)m0 * lda;
    const float*  B = B0 + (size_t)e * sBe;
    uint32_t AsU = s2u(As), BsU = s2u(Bs);

    int ar = tid >> 1, acol = (tid & 1) * 16;
    int br = tid >> 3, sg = tid & 7;
    int bcolg = (sg < 4) ? (n0 + sg * 16) : (halfOff + n0 + (sg - 4) * 16);
    int bcols = (sg < 4) ? (sg * 16) : (64 + (sg - 4) * 16);
    const __half* Ag = A + (size_t)ar * lda + acol;
    const float*  Bg = B + (size_t)br * ldb + bcolg;

    float accg[4][2][4] = {}, accu[4][2][4] = {};
    uint2 rbh[4];

    auto cpaA = [&](int b, int k0) {
        uint32_t d = AsU + (uint32_t)(b * ABUF + ar * LDA_S + acol) * 2;
        const __half* s = Ag + k0;
        CPA16(d, s);
        CPA16(d + 16, s + 8);
    };
    auto ldgB = [&](int k0) {
        const float4* bp = (const float4*)(Bg + (size_t)k0 * ldb);
        rbh[0] = f4h(bp[0]); rbh[1] = f4h(bp[1]); rbh[2] = f4h(bp[2]); rbh[3] = f4h(bp[3]);
    };
    auto stsB = [&](int b) {
        uint4* bd = (uint4*)(Bs + b * BBUF + br * LDB_S + bcols);
        bd[0] = make_uint4(rbh[0].x, rbh[0].y, rbh[1].x, rbh[1].y);
        bd[1] = make_uint4(rbh[2].x, rbh[2].y, rbh[3].x, rbh[3].y);
    };

    int NC = Kdim / 32;
    ldgB(0);
    cpaA(0, 0); CP_COMMIT();
    for (int i = 0; i < NC; i++) {
        int b = i & 1;
        stsB(b);
        bool more = (i + 1 < NC);
        if (more) { cpaA(b ^ 1, (i + 1) * 32); CP_COMMIT(); CP_WAIT1(); }
        else CP_WAIT0();
        __syncthreads();
        if (more) ldgB((i + 1) * 32);

        uint32_t ab = AsU + (uint32_t)(b * ABUF) * 2;
        uint32_t bb = BsU + (uint32_t)(b * BBUF) * 2;
        #pragma unroll
        for (int ks = 0; ks < 32; ks += 16) {
            uint32_t af[4][4];
            #pragma unroll
            for (int mi = 0; mi < 4; mi++) {
                int r = mw * 64 + mi * 16 + (lane & 15);
                LDSM4(af[mi], ab + (uint32_t)(r * LDA_S + ks + (lane >> 4) * 8) * 2);
            }
            uint32_t bgf[4], buf[4];
            int kr = ks + (lane & 15);
            LDSM4T(bgf, bb + (uint32_t)(kr * LDB_S + nw * 16 + (lane >> 4) * 8) * 2);
            LDSM4T(buf, bb + (uint32_t)(kr * LDB_S + 64 + nw * 16 + (lane >> 4) * 8) * 2);
            #pragma unroll
            for (int mi = 0; mi < 4; mi++) {
                MMA16816(accg[mi][0], af[mi], bgf[0], bgf[1]);
                MMA16816(accg[mi][1], af[mi], bgf[2], bgf[3]);
                MMA16816(accu[mi][0], af[mi], buf[0], buf[1]);
                MMA16816(accu[mi][1], af[mi], buf[2], buf[3]);
            }
        }
        __syncthreads();
    }

    int g = lane >> 2, c = lane & 3;
    #pragma unroll
    for (int mi = 0; mi < 4; mi++) {
        #pragma unroll
        for (int j = 0; j < 2; j++) {
            float* G = accg[mi][j];
            float* U = accu[mi][j];
            int col = n0 + nw * 16 + j * 8 + 2 * c;
            int r0 = m0 + mw * 64 + mi * 16 + g;
            float s0 = G[0] / (1.f + expf(-G[0])) * U[0];
            float s1 = G[1] / (1.f + expf(-G[1])) * U[1];
            float s2 = G[2] / (1.f + expf(-G[2])) * U[2];
            float s3 = G[3] / (1.f + expf(-G[3])) * U[3];
            *(__half2*)(C0 + (size_t)e * sCe + (size_t)r0 * ldc + col) = __floats2half2_rn(s0, s1);
            *(__half2*)(C0 + (size_t)e * sCe + (size_t)(r0 + 8) * ldc + col) = __floats2half2_rn(s2, s3);
        }
    }
}

// ---------------- Plain GEMM: A fp16 (cp.async), B fp32 (reg cvt), templated out ----------------
template <typename OutT>
__global__ __launch_bounds__(256, 2)
void gemm2_mma(const __half* __restrict__ A0, int lda, size_t sAe,
               const float* __restrict__ B0, int ldb, size_t sBe,
               OutT* __restrict__ C0, int ldc, size_t sCe,
               int Kdim, const int* __restrict__ cnt)
{
    __shared__ __align__(16) __half As[2 * ABUF];
    __shared__ __align__(16) __half Bs[2 * BBUF];

    int e = blockIdx.z;
    int m0 = blockIdx.y * 128;
    if (cnt && m0 >= cnt[e]) return;
    int n0 = blockIdx.x * 128;

    int tid = threadIdx.x;
    int warp = tid >> 5, lane = tid & 31;
    int mw = warp & 1, nw = warp >> 1;

    const __half* A = A0 + (size_t)e * sAe + (size_t)m0 * lda;
    const float*  B = B0 + (size_t)e * sBe;
    uint32_t AsU = s2u(As), BsU = s2u(Bs);

    int ar = tid >> 1, acol = (tid & 1) * 16;
    int br = tid >> 3, sg = tid & 7;
    const __half* Ag = A + (size_t)ar * lda + acol;
    const float*  Bg = B + (size_t)br * ldb + n0 + sg * 16;

    float acc[4][4][4] = {};
    uint2 rbh[4];

    auto cpaA = [&](int b, int k0) {
        uint32_t d = AsU + (uint32_t)(b * ABUF + ar * LDA_S + acol) * 2;
        const __half* s = Ag + k0;
        CPA16(d, s);
        CPA16(d + 16, s + 8);
    };
    auto ldgB = [&](int k0) {
        const float4* bp = (const float4*)(Bg + (size_t)k0 * ldb);
        rbh[0] = f4h(bp[0]); rbh[1] = f4h(bp[1]); rbh[2] = f4h(bp[2]); rbh[3] = f4h(bp[3]);
    };
    auto stsB = [&](int b) {
        uint4* bd = (uint4*)(Bs + b * BBUF + br * LDB_S + sg * 16);
        bd[0] = make_uint4(rbh[0].x, rbh[0].y, rbh[1].x, rbh[1].y);
        bd[1] = make_uint4(rbh[2].x, rbh[2].y, rbh[3].x, rbh[3].y);
    };

    int NC = Kdim / 32;
    ldgB(0);
    cpaA(0, 0); CP_COMMIT();
    for (int i = 0; i < NC; i++) {
        int b = i & 1;
        stsB(b);
        bool more = (i + 1 < NC);
        if (more) { cpaA(b ^ 1, (i + 1) * 32); CP_COMMIT(); CP_WAIT1(); }
        else CP_WAIT0();
        __syncthreads();
        if (more) ldgB((i + 1) * 32);

        uint32_t ab = AsU + (uint32_t)(b * ABUF) * 2;
        uint32_t bb = BsU + (uint32_t)(b * BBUF) * 2;
        #pragma unroll
        for (int ks = 0; ks < 32; ks += 16) {
            uint32_t af[4][4];
            #pragma unroll
            for (int mi = 0; mi < 4; mi++) {
                int r = mw * 64 + mi * 16 + (lane & 15);
                LDSM4(af[mi], ab + (uint32_t)(r * LDA_S + ks + (lane >> 4) * 8) * 2);
            }
            uint32_t bf0[4], bf1[4];
            int kr = ks + (lane & 15);
            LDSM4T(bf0, bb + (uint32_t)(kr * LDB_S + nw * 32 + (lane >> 4) * 8) * 2);
            LDSM4T(bf1, bb + (uint32_t)(kr * LDB_S + nw * 32 + 16 + (lane >> 4) * 8) * 2);
            #pragma unroll
            for (int mi = 0; mi < 4; mi++) {
                MMA16816(acc[mi][0], af[mi], bf0[0], bf0[1]);
                MMA16816(acc[mi][1], af[mi], bf0[2], bf0[3]);
                MMA16816(acc[mi][2], af[mi], bf1[0], bf1[1]);
                MMA16816(acc[mi][3], af[mi], bf1[2], bf1[3]);
            }
        }
        __syncthreads();
    }

    int g = lane >> 2, c = lane & 3;
    #pragma unroll
    for (int mi = 0; mi < 4; mi++) {
        #pragma unroll
        for (int j = 0; j < 4; j++) {
            float* D = acc[mi][j];
            int col = n0 + nw * 32 + j * 8 + 2 * c;
            int r0 = m0 + mw * 64 + mi * 16 + g;
            OutT* Cb = C0 + (size_t)e * sCe;
            if constexpr (sizeof(OutT) == 4) {
                *(float2*)((float*)Cb + (size_t)r0 * ldc + col) = make_float2(D[0], D[1]);
                *(float2*)((float*)Cb + (size_t)(r0 + 8) * ldc + col) = make_float2(D[2], D[3]);
            } else {
                *(__half2*)((__half*)Cb + (size_t)r0 * ldc + col) = __floats2half2_rn(D[0], D[1]);
                *(__half2*)((__half*)Cb + (size_t)(r0 + 8) * ldc + col) = __floats2half2_rn(D[2], D[3]);
            }
        }
    }
}

// ---------------- Combine (eo fp16) ----------------
__global__ void combine_kernel(float* __restrict__ out) {
    int t = blockIdx.x;
    int h = threadIdx.x;
    int ids[TOPK], pos[TOPK]; float w[TOPK];
    #pragma unroll
    for (int k = 0; k < TOPK; k++) {
        ids[k] = g_ids[t * TOPK + k];
        pos[k] = g_pos[t * TOPK + k];
        w[k]   = g_wts[t * TOPK + k];
    }
    float4* o4 = (float4*)(out + (size_t)t * HDIM);
    float4 acc = o4[h];
    #pragma unroll
    for (int k = 0; k < TOPK; k++) {
        if (pos[k] < CAP) {
            const uint2* v2 = (const uint2*)(g_eo16 + ((size_t)ids[k] * CAP + pos[k]) * HDIM);
            uint2 u = v2[h];
            float2 fa = __half22float2(*(__half2*)&u.x);
            float2 fb = __half22float2(*(__half2*)&u.y);
            acc.x = fmaf(w[k], fa.x, acc.x);
            acc.y = fmaf(w[k], fa.y, acc.y);
            acc.z = fmaf(w[k], fb.x, acc.z);
            acc.w = fmaf(w[k], fb.y, acc.w);
        }
    }
    o4[h] = acc;
}

// ---------------- Launch ----------------
extern "C" void kernel_launch(void* const* d_in, const int* in_sizes, int n_in,
                              void* d_out, int out_size)
{
    const float* x      = (const float*)d_in[0];
    const float* gate_w = (const float*)d_in[1];
    const float* bias   = (const float*)d_in[2];
    const float* w13    = (const float*)d_in[3];
    const float* w2     = (const float*)d_in[4];
    const float* sw13   = (const float*)d_in[5];
    const float* sw2    = (const float*)d_in[6];
    float* out = (float*)d_out;

    __half *buf16, *act16, *eo16, *x16, *acts16;
    float* logP; int* cnt;
    cudaGetSymbolAddress((void**)&buf16,  g_buf16);
    cudaGetSymbolAddress((void**)&act16,  g_act16);
    cudaGetSymbolAddress((void**)&eo16,   g_eo16);
    cudaGetSymbolAddress((void**)&x16,    g_x16);
    cudaGetSymbolAddress((void**)&acts16, g_acts16);
    cudaGetSymbolAddress((void**)&logP,   g_logP);
    cudaGetSymbolAddress((void**)&cnt,    g_cnt);

    static cudaStream_t s2 = nullptr;
    static cudaEvent_t evA = nullptr, evSh = nullptr;
    if (!s2) {
        cudaStreamCreateWithFlags(&s2, cudaStreamNonBlocking);
        cudaEventCreateWithFlags(&evA,  cudaEventDisableTiming);
        cudaEventCreateWithFlags(&evSh, cudaEventDisableTiming);
    }

    // fork
    cudaEventRecord(evA, 0);
    cudaStreamWaitEvent(s2, evA, 0);

    // ---- side stream: shared-expert chain ----
    conv16_kernel<<<(T_TOK * HDIM / 4 + 255) / 256, 256, 0, s2>>>(x, x16, T_TOK * HDIM / 4);
    gemm13_mma<<<dim3(FSH / 64, T_TOK / 128, 1), 256, 0, s2>>>(
        x16, HDIM, 0, sw13, 2 * FSH, 0, FSH, acts16, FSH, 0, HDIM, nullptr);
    gemm2_mma<float><<<dim3(HDIM / 128, T_TOK / 128, 1), 256, 0, s2>>>(
        acts16, FSH, 0, sw2, HDIM, 0, out, HDIM, 0, FSH, nullptr);
    cudaEventRecord(evSh, s2);

    // ---- main stream: routing + routed experts ----
    gate_logits_kernel<<<dim3(T_TOK / 16, KSPLIT), 256>>>(x, gate_w, logP);
    zero_cnt_kernel<<<1, 64>>>();
    topk_kernel<<<T_TOK / 4, 256>>>(logP, bias);
    scatter16_kernel<<<T_TOK * TOPK, 128>>>(x);

    gemm13_mma<<<dim3(FDIM / 64, CAP / 128, NEXP), 256>>>(
        buf16, HDIM, (size_t)CAP * HDIM,
        w13, 2 * FDIM, (size_t)HDIM * 2 * FDIM, FDIM,
        act16, FDIM, (size_t)CAP * FDIM,
        HDIM, cnt);

    gemm2_mma<__half><<<dim3(HDIM / 128, CAP / 128, NEXP), 256>>>(
        act16, FDIM, (size_t)CAP * FDIM,
        w2, HDIM, (size_t)FDIM * HDIM,
        eo16, HDIM, (size_t)CAP * HDIM,
        FDIM, cnt);

    // join shared branch, then combine
    cudaStreamWaitEvent(0, evSh, 0);
    combine_kernel<<<T_TOK, 256>>>(out);
}